// round 8
// baseline (speedup 1.0000x reference)
#include <cuda_runtime.h>
#include <cuda_bf16.h>
#include <math.h>
#include <stdint.h>

// Problem constants
#define Bq   4
#define Tq   8192
#define Dq   1024
#define DS   64
#define CHq  128
#define Cq   64
#define ROWS (Bq * Tq)
#define OUT_ELEMS ((size_t)ROWS * Dq)

// ---------------- scratch (static device globals) ----------------
__device__ __nv_bfloat16 g_xh[ROWS * Dq],  g_xl[ROWS * Dq];    // x split
__device__ __nv_bfloat16 g_xsh[ROWS * Dq], g_xsl[ROWS * Dq];   // x_shift split
__device__ __nv_bfloat16 g_wshh[Dq * Dq],  g_wshl[Dq * Dq];    // Wshift [k][n]
__device__ __nv_bfloat16 g_woh[DS * Dq],   g_wol[DS * Dq];     // Wo [k=64][n=1024]
__device__ __nv_bfloat16 g_W2h[Dq * 128],  g_W2l[Dq * 128];    // g*[Wk|Wv] interleaved [k][128]
__device__ __nv_bfloat16 g_hsh[ROWS * DS], g_hsl[ROWS * DS];   // hs split
__device__ float g_wkv[ROWS * DS];
__device__ float g_mu[ROWS], g_rstd[ROWS];
__device__ float g_ps[32 * ROWS], g_ps2[32 * ROWS];            // LN stat partials
__device__ float g_csum[128], g_bsum[128], g_gate[Dq];
__device__ float g_wvec[DS], g_efvec[DS];
__device__ float g_c1[CHq * DS], g_c2[Cq * DS], g_cs[Bq * Cq * DS];

// ---------------------------------------------------------------------------
__device__ __forceinline__ void split2(float v0, float v1, __nv_bfloat162& h, __nv_bfloat162& l) {
    __nv_bfloat16 h0 = __float2bfloat16(v0);
    __nv_bfloat16 h1 = __float2bfloat16(v1);
    __nv_bfloat16 l0 = __float2bfloat16(v0 - __bfloat162float(h0));
    __nv_bfloat16 l1 = __float2bfloat16(v1 - __bfloat162float(h1));
    h = __halves2bfloat162(h0, h1);
    l = __halves2bfloat162(l0, l1);
}

__global__ void conv_split(const float* __restrict__ in, __nv_bfloat16* __restrict__ hi,
                           __nv_bfloat16* __restrict__ lo) {
    int i = blockIdx.x * blockDim.x + threadIdx.x;
    float4 v = ((const float4*)in)[i];
    __nv_bfloat162 h0, l0, h1, l1;
    split2(v.x, v.y, h0, l0);
    split2(v.z, v.w, h1, l1);
    ((__nv_bfloat162*)hi)[2 * i]     = h0;
    ((__nv_bfloat162*)hi)[2 * i + 1] = h1;
    ((__nv_bfloat162*)lo)[2 * i]     = l0;
    ((__nv_bfloat162*)lo)[2 * i + 1] = l1;
}

// ---------------------------------------------------------------------------
__global__ void prep_kernel(const float* __restrict__ td, const float* __restrict__ tf,
                            const float* __restrict__ Wk, const float* __restrict__ Wv,
                            const float* __restrict__ ln_g, const float* __restrict__ ln_b,
                            const float* __restrict__ sg) {
    int n = threadIdx.x;  // 128 threads
    if (n < DS) {
        g_wvec[n]  = expf(td[n]);
        g_efvec[n] = expf(tf[n]);
    }
    for (int i = n; i < Dq; i += 128)
        g_gate[i] = 1.f / (1.f + expf(-sg[i]));

    int j = n >> 1, isv = n & 1;
    float cs = 0.f, bs = 0.f;
    for (int k = 0; k < Dq; k++) {
        float wv = isv ? Wv[k * DS + j] : Wk[k * DS + j];
        float gk = ln_g[k];
        float w2 = gk * wv;
        __nv_bfloat16 h = __float2bfloat16(w2);
        g_W2h[k * 128 + n] = h;
        g_W2l[k * 128 + n] = __float2bfloat16(w2 - __bfloat162float(h));
        cs += w2;
        bs += ln_b[k] * wv;
    }
    g_csum[n] = cs;
    g_bsum[n] = bs;
}

// ---------------------------------------------------------------------------
__global__ void coef_kernel(const float* __restrict__ td) {
    int ch = blockIdx.x;
    int d  = threadIdx.x;
    __shared__ float p[CHq];
    float w = expf(td[ch]);
    p[d] = (d == 0) ? 1.f : 0.f;
    __syncthreads();
    for (int s = 1; s < CHq; s++) {
        float tmp = (d >= s) ? p[d - s] : 0.f;
        __syncthreads();
        if (d >= s) p[d] += w * tmp;
        __syncthreads();
    }
    g_c1[d * DS + ch] = p[d];

    float wc = expf(128.f * td[ch]);
    __syncthreads();
    if (d < Cq) p[d] = (d == 0) ? 1.f : 0.f;
    __syncthreads();
    for (int s = 1; s < Cq; s++) {
        float tmp = (d >= s && d < Cq) ? p[d - s] : 0.f;
        __syncthreads();
        if (d >= s && d < Cq) p[d] += wc * tmp;
        __syncthreads();
    }
    if (d < Cq) g_c2[d * DS + ch] = p[d];
}

// ---------------------------------------------------------------------------
// mma.sync machinery
// ---------------------------------------------------------------------------
__device__ __forceinline__ unsigned sptr(const void* p) {
    return (unsigned)__cvta_generic_to_shared(p);
}
__device__ __forceinline__ void ldsm4(unsigned* r, unsigned a) {
    asm volatile("ldmatrix.sync.aligned.m8n8.x4.shared.b16 {%0,%1,%2,%3},[%4];"
                 : "=r"(r[0]), "=r"(r[1]), "=r"(r[2]), "=r"(r[3]) : "r"(a));
}
__device__ __forceinline__ void ldsm4t(unsigned* r, unsigned a) {
    asm volatile("ldmatrix.sync.aligned.m8n8.x4.trans.shared.b16 {%0,%1,%2,%3},[%4];"
                 : "=r"(r[0]), "=r"(r[1]), "=r"(r[2]), "=r"(r[3]) : "r"(a));
}
__device__ __forceinline__ void mma_bf(float* c, const unsigned* a, unsigned b0, unsigned b1) {
    asm volatile("mma.sync.aligned.m16n8k16.row.col.f32.bf16.bf16.f32 "
                 "{%0,%1,%2,%3},{%4,%5,%6,%7},{%8,%9},{%0,%1,%2,%3};"
                 : "+f"(c[0]), "+f"(c[1]), "+f"(c[2]), "+f"(c[3])
                 : "r"(a[0]), "r"(a[1]), "r"(a[2]), "r"(a[3]), "r"(b0), "r"(b1));
}
__device__ __forceinline__ void cp16(unsigned s, const void* g) {
    asm volatile("cp.async.cg.shared.global [%0],[%1],16;\n" :: "r"(s), "l"(g));
}

#define AP 24    // A smem pitch (bf16), 48B rows (validated conflict-free)
#define BP 136   // B smem pitch (bf16), 272B rows (validated conflict-free)
#define ABYT (128 * AP * 2)            // 6144
#define BBYT (16 * BP * 2)             // 4352
#define STG  (2 * ABYT + 2 * BBYT)     // 20992 per stage
#define NSTG 3
#define SMEM_DYN (NSTG * STG)          // 62976

// MODE 0: x_shift GEMM + gate-mix + LN-partials epilogue
// MODE 1: kv GEMM (LN folded) + wkv epilogue
// MODE 2: out GEMM (hs @ Wo)
template <int MODE>
__global__ __launch_bounds__(256, 2)
void gemm_tc(const float* __restrict__ x, float* __restrict__ out) {
    constexpr int KTOT = (MODE == 2) ? 64 : 1024;
    constexpr int NKB = KTOT / 16;

    extern __shared__ __align__(1024) char smraw[];
    const unsigned sbase = sptr(smraw);

    const int t = threadIdx.x;
    const int lane = t & 31;
    const int wid = t >> 5;
    const int wm = (wid >> 2) * 64;
    const int wn = (wid & 3) * 32;
    const int bm = (MODE == 1 ? blockIdx.x : blockIdx.y) * 128;
    const int bn = (MODE == 1 ? 0 : blockIdx.x * 128);

    // ---- load geometry (R5-validated) ----
    const __nv_bfloat16 *pAh, *pAl, *pBh, *pBl;
    size_t bpitch;
    {
        int r = bm + (t >> 1);
        if (MODE == 0) {
            int s = ((r >> 13) << 13) | (((r & (Tq - 1)) + Tq / 2) & (Tq - 1));
            pAh = g_xh + (size_t)s * Dq;
            pAl = g_xl + (size_t)s * Dq;
        } else if (MODE == 1) {
            pAh = g_xsh + (size_t)r * Dq;
            pAl = g_xsl + (size_t)r * Dq;
        } else {
            pAh = g_hsh + (size_t)r * DS;
            pAl = g_hsl + (size_t)r * DS;
        }
        pAh += (t & 1) * 8;
        pAl += (t & 1) * 8;
    }
    if (MODE == 0)      { pBh = g_wshh; pBl = g_wshl; bpitch = Dq;  }
    else if (MODE == 1) { pBh = g_W2h;  pBl = g_W2l;  bpitch = 128; }
    else                { pBh = g_woh;  pBl = g_wol;  bpitch = Dq;  }
    pBh += (size_t)(t >> 4) * bpitch + bn + (t & 15) * 8;
    pBl += (size_t)(t >> 4) * bpitch + bn + (t & 15) * 8;

    const unsigned aST = (unsigned)(((t >> 1) * AP + (t & 1) * 8) * 2);
    const unsigned bST = (unsigned)(((t >> 4) * BP + (t & 15) * 8) * 2);
    const unsigned aoff = (unsigned)(((lane & 15) * AP + ((lane >> 4) << 3)) * 2);
    const unsigned boff = (unsigned)(((lane & 15) * BP + wn + ((lane >> 4) << 3)) * 2);

    float acc[4][4][4];
#pragma unroll
    for (int i = 0; i < 4; i++)
#pragma unroll
        for (int j = 0; j < 4; j++)
#pragma unroll
            for (int e = 0; e < 4; e++) acc[i][j][e] = 0.f;

    auto LOAD = [&](int kc) {
        const unsigned s0 = sbase + (unsigned)((kc % NSTG) * STG);
        cp16(s0 + aST,        pAh + (size_t)kc * 16);
        cp16(s0 + ABYT + aST, pAl + (size_t)kc * 16);
        const unsigned b0 = s0 + 2 * ABYT;
        cp16(b0 + bST,        pBh + (size_t)kc * 16 * bpitch);
        cp16(b0 + BBYT + bST, pBl + (size_t)kc * 16 * bpitch);
        asm volatile("cp.async.commit_group;" ::: "memory");
    };

    // ---- 3-stage pipeline, one barrier per chunk, one group in flight ----
    LOAD(0);
    if (NKB > 1) LOAD(1);
    for (int kc = 0; kc < NKB; kc++) {
        if (kc + 1 < NKB) asm volatile("cp.async.wait_group 1;" ::: "memory");
        else              asm volatile("cp.async.wait_group 0;" ::: "memory");
        __syncthreads();
        if (kc + 2 < NKB) LOAD(kc + 2);   // overlaps compute; stage safe per barrier above

        const unsigned aHi = sbase + (unsigned)((kc % NSTG) * STG);
        const unsigned aLo = aHi + ABYT;
        const unsigned bHi = aHi + 2 * ABYT;
        const unsigned bLo = bHi + BBYT;

        unsigned ah[4][4], al[4][4], bh[2][4], bl[2][4];
#pragma unroll
        for (int mt = 0; mt < 4; mt++) {
            unsigned off = (unsigned)((wm + mt * 16) * AP * 2) + aoff;
            ldsm4(ah[mt], aHi + off);
            ldsm4(al[mt], aLo + off);
        }
#pragma unroll
        for (int ng = 0; ng < 2; ng++) {
            unsigned off = boff + ng * 32;
            ldsm4t(bh[ng], bHi + off);
            ldsm4t(bl[ng], bLo + off);
        }
#pragma unroll
        for (int mt = 0; mt < 4; mt++)
#pragma unroll
            for (int nt = 0; nt < 4; nt++) {
                const int ng = nt >> 1, p = (nt & 1) * 2;
                mma_bf(acc[mt][nt], ah[mt], bh[ng][p], bh[ng][p + 1]);
                mma_bf(acc[mt][nt], ah[mt], bl[ng][p], bl[ng][p + 1]);
                mma_bf(acc[mt][nt], al[mt], bh[ng][p], bh[ng][p + 1]);
            }
    }

    // ---------------- epilogue ----------------
#pragma unroll
    for (int mt = 0; mt < 4; mt++) {
        const int r0 = bm + wm + mt * 16 + (lane >> 2);
        if (MODE == 0) {
            float s0 = 0.f, s20 = 0.f, s1 = 0.f, s21 = 0.f;
#pragma unroll
            for (int nt = 0; nt < 4; nt++) {
                const int col = bn + wn + nt * 8 + (lane & 3) * 2;
                float2 g2 = *(const float2*)&g_gate[col];
                float2 xv = *(const float2*)&x[(size_t)r0 * Dq + col];
                float ox = fmaf(acc[mt][nt][0] - xv.x, g2.x, xv.x);
                float oy = fmaf(acc[mt][nt][1] - xv.y, g2.y, xv.y);
                s0 += ox + oy;
                s20 += ox * ox + oy * oy;
                __nv_bfloat162 h, l;
                split2(ox, oy, h, l);
                *(__nv_bfloat162*)&g_xsh[(size_t)r0 * Dq + col] = h;
                *(__nv_bfloat162*)&g_xsl[(size_t)r0 * Dq + col] = l;
                float2 xw = *(const float2*)&x[(size_t)(r0 + 8) * Dq + col];
                ox = fmaf(acc[mt][nt][2] - xw.x, g2.x, xw.x);
                oy = fmaf(acc[mt][nt][3] - xw.y, g2.y, xw.y);
                s1 += ox + oy;
                s21 += ox * ox + oy * oy;
                split2(ox, oy, h, l);
                *(__nv_bfloat162*)&g_xsh[(size_t)(r0 + 8) * Dq + col] = h;
                *(__nv_bfloat162*)&g_xsl[(size_t)(r0 + 8) * Dq + col] = l;
            }
#pragma unroll
            for (int o = 1; o <= 2; o <<= 1) {
                s0  += __shfl_xor_sync(0xffffffffu, s0, o);
                s20 += __shfl_xor_sync(0xffffffffu, s20, o);
                s1  += __shfl_xor_sync(0xffffffffu, s1, o);
                s21 += __shfl_xor_sync(0xffffffffu, s21, o);
            }
            if ((lane & 3) == 0) {
                const int slice = blockIdx.x * 4 + (wid & 3);
                g_ps[(size_t)slice * ROWS + r0]      = s0;
                g_ps2[(size_t)slice * ROWS + r0]     = s20;
                g_ps[(size_t)slice * ROWS + r0 + 8]  = s1;
                g_ps2[(size_t)slice * ROWS + r0 + 8] = s21;
            }
        } else if (MODE == 1) {
            const float mu0 = g_mu[r0], rs0 = g_rstd[r0];
            const float mu1 = g_mu[r0 + 8], rs1 = g_rstd[r0 + 8];
#pragma unroll
            for (int nt = 0; nt < 4; nt++) {
                const int col = wn + nt * 8 + (lane & 3) * 2;
                const int ch = col >> 1;
                const float cs0 = g_csum[col], cs1 = g_csum[col + 1];
                const float bs0 = g_bsum[col], bs1 = g_bsum[col + 1];
                const float ef = g_efvec[ch];
                {
                    float kk = rs0 * (acc[mt][nt][0] - mu0 * cs0) + bs0;
                    float vv = rs0 * (acc[mt][nt][1] - mu0 * cs1) + bs1;
                    float sig = 1.f / (1.f + expf(-kk));
                    g_wkv[(size_t)r0 * DS + ch] = expf(-ef * sig) * vv;
                }
                {
                    float kk = rs1 * (acc[mt][nt][2] - mu1 * cs0) + bs0;
                    float vv = rs1 * (acc[mt][nt][3] - mu1 * cs1) + bs1;
                    float sig = 1.f / (1.f + expf(-kk));
                    g_wkv[(size_t)(r0 + 8) * DS + ch] = expf(-ef * sig) * vv;
                }
            }
        } else {
#pragma unroll
            for (int nt = 0; nt < 4; nt++) {
                const int col = bn + wn + nt * 8 + (lane & 3) * 2;
                float2 o0 = {acc[mt][nt][0], acc[mt][nt][1]};
                float2 o1 = {acc[mt][nt][2], acc[mt][nt][3]};
                *(float2*)&out[(size_t)r0 * Dq + col] = o0;
                *(float2*)&out[(size_t)(r0 + 8) * Dq + col] = o1;
            }
        }
    }
}

// ---------------------------------------------------------------------------
__global__ void finalize_stats() {
    int row = blockIdx.x * 256 + threadIdx.x;
    float s = 0.f, s2 = 0.f;
#pragma unroll
    for (int sl = 0; sl < 32; sl++) {
        s  += g_ps[(size_t)sl * ROWS + row];
        s2 += g_ps2[(size_t)sl * ROWS + row];
    }
    float mu  = s * (1.f / 1024.f);
    float var = s2 * (1.f / 1024.f) - mu * mu;
    g_mu[row]   = mu;
    g_rstd[row] = rsqrtf(var + 1e-5f);
}

// ---------------------------------------------------------------------------
__global__ void scan_kernel() {
    int bc = blockIdx.x;
    int ch = threadIdx.x;
    float w = g_wvec[ch];
    size_t base = (size_t)bc * CHq * DS + ch;
    float h = 0.f;
    for (int i = 0; i < CHq; i++) {
        h = fmaf(h, w, g_wkv[base + (size_t)i * DS]);
        __nv_bfloat16 hh = __float2bfloat16(h);
        g_hsh[base + (size_t)i * DS] = hh;
        g_hsl[base + (size_t)i * DS] = __float2bfloat16(h - __bfloat162float(hh));
    }
}

// ---------------------------------------------------------------------------
__global__ void cstate_kernel() {
    int bc = blockIdx.x;
    int ch = threadIdx.x;
    const float* base = g_wkv + (size_t)bc * CHq * DS + ch;
    float s = 0.f;
    for (int d = 0; d < CHq; d++)
        s = fmaf(g_c1[d * DS + ch], base[(size_t)(CHq - 1 - d) * DS], s);
    g_cs[bc * DS + ch] = s;
}

__global__ void lstate_kernel(float* __restrict__ outls) {
    int b = blockIdx.x;
    int ch = threadIdx.x;
    float s = 0.f;
    for (int e = 0; e < Cq; e++)
        s = fmaf(g_c2[e * DS + ch], g_cs[((size_t)b * Cq + (Cq - 1 - e)) * DS + ch], s);
    outls[b * DS + ch] = s;
}

// ---------------------------------------------------------------------------
extern "C" void kernel_launch(void* const* d_in, const int* in_sizes, int n_in,
                              void* d_out, int out_size) {
    const float* x   = (const float*)d_in[0];
    const float* td  = (const float*)d_in[1];
    const float* tf  = (const float*)d_in[2];
    const float* Wk  = (const float*)d_in[3];
    const float* Wv  = (const float*)d_in[4];
    const float* Wo  = (const float*)d_in[5];
    const float* Wsh = (const float*)d_in[6];
    const float* sg  = (const float*)d_in[7];
    const float* lng = (const float*)d_in[8];
    const float* lnb = (const float*)d_in[9];
    float* out = (float*)d_out;

    __nv_bfloat16 *xh, *xl, *wshh, *wshl, *woh, *wol;
    cudaGetSymbolAddress((void**)&xh,   g_xh);
    cudaGetSymbolAddress((void**)&xl,   g_xl);
    cudaGetSymbolAddress((void**)&wshh, g_wshh);
    cudaGetSymbolAddress((void**)&wshl, g_wshl);
    cudaGetSymbolAddress((void**)&woh,  g_woh);
    cudaGetSymbolAddress((void**)&wol,  g_wol);

    cudaFuncSetAttribute(gemm_tc<0>, cudaFuncAttributeMaxDynamicSharedMemorySize, SMEM_DYN);
    cudaFuncSetAttribute(gemm_tc<1>, cudaFuncAttributeMaxDynamicSharedMemorySize, SMEM_DYN);
    cudaFuncSetAttribute(gemm_tc<2>, cudaFuncAttributeMaxDynamicSharedMemorySize, SMEM_DYN);

    // launch order chosen so gemm_tc<0> is the 4th launch (ncu samples #4)
    conv_split<<<(ROWS * Dq / 4) / 256, 256>>>(x, xh, xl);               // 1
    conv_split<<<(Dq * Dq / 4) / 256, 256>>>(Wsh, wshh, wshl);           // 2
    prep_kernel<<<1, 128>>>(td, tf, Wk, Wv, lng, lnb, sg);               // 3
    gemm_tc<0><<<dim3(Dq / 128, ROWS / 128), 256, SMEM_DYN>>>(x, out);   // 4 <- profiled
    finalize_stats<<<ROWS / 256, 256>>>();                               // 5
    coef_kernel<<<64, 128>>>(td);                                        // 6
    conv_split<<<(DS * Dq / 4) / 256, 256>>>(Wo, woh, wol);              // 7
    gemm_tc<1><<<ROWS / 128, 256, SMEM_DYN>>>(x, out);                   // 8
    scan_kernel<<<Bq * Cq, DS>>>();                                      // 9
    gemm_tc<2><<<dim3(Dq / 128, ROWS / 128), 256, SMEM_DYN>>>(x, out);   // 10
    cstate_kernel<<<Bq * Cq, DS>>>();                                    // 11
    if ((size_t)out_size >= OUT_ELEMS + (size_t)Bq * DS) {
        lstate_kernel<<<Bq, DS>>>(out + OUT_ELEMS);                      // 12
    }
}

// round 9
// speedup vs baseline: 1.0427x; 1.0427x over previous
#include <cuda_runtime.h>
#include <cuda_bf16.h>
#include <math.h>
#include <stdint.h>

// Problem constants
#define Bq   4
#define Tq   8192
#define Dq   1024
#define DS   64
#define CHq  128
#define Cq   64
#define ROWS (Bq * Tq)
#define OUT_ELEMS ((size_t)ROWS * Dq)

// ---------------- scratch (static device globals) ----------------
__device__ __nv_bfloat16 g_xh[ROWS * Dq],  g_xl[ROWS * Dq];    // x split
__device__ __nv_bfloat16 g_xsh[ROWS * Dq], g_xsl[ROWS * Dq];   // x_shift split
__device__ __nv_bfloat16 g_wshh[Dq * Dq],  g_wshl[Dq * Dq];    // Wshift [k][n]
__device__ __nv_bfloat16 g_woh[DS * Dq],   g_wol[DS * Dq];     // Wo [k=64][n=1024]
__device__ __nv_bfloat16 g_W2h[Dq * 128],  g_W2l[Dq * 128];    // g*[Wk|Wv] interleaved [k][128]
__device__ __nv_bfloat16 g_hsh[ROWS * DS], g_hsl[ROWS * DS];   // hs split
__device__ float g_wkv[ROWS * DS];
__device__ float g_mu[ROWS], g_rstd[ROWS];
__device__ float g_ps[32 * ROWS], g_ps2[32 * ROWS];            // LN stat partials
__device__ float g_csum[128], g_bsum[128], g_gate[Dq];
__device__ float g_wvec[DS], g_efvec[DS];
__device__ float g_c1[CHq * DS], g_c2[Cq * DS], g_cs[Bq * Cq * DS];

// ---------------------------------------------------------------------------
__device__ __forceinline__ void split2(float v0, float v1, __nv_bfloat162& h, __nv_bfloat162& l) {
    __nv_bfloat16 h0 = __float2bfloat16(v0);
    __nv_bfloat16 h1 = __float2bfloat16(v1);
    __nv_bfloat16 l0 = __float2bfloat16(v0 - __bfloat162float(h0));
    __nv_bfloat16 l1 = __float2bfloat16(v1 - __bfloat162float(h1));
    h = __halves2bfloat162(h0, h1);
    l = __halves2bfloat162(l0, l1);
}

__global__ void conv_split(const float* __restrict__ in, __nv_bfloat16* __restrict__ hi,
                           __nv_bfloat16* __restrict__ lo) {
    int i = blockIdx.x * blockDim.x + threadIdx.x;
    float4 v = ((const float4*)in)[i];
    __nv_bfloat162 h0, l0, h1, l1;
    split2(v.x, v.y, h0, l0);
    split2(v.z, v.w, h1, l1);
    ((__nv_bfloat162*)hi)[2 * i]     = h0;
    ((__nv_bfloat162*)hi)[2 * i + 1] = h1;
    ((__nv_bfloat162*)lo)[2 * i]     = l0;
    ((__nv_bfloat162*)lo)[2 * i + 1] = l1;
}

// ---------------------------------------------------------------------------
__global__ void prep_kernel(const float* __restrict__ td, const float* __restrict__ tf,
                            const float* __restrict__ Wk, const float* __restrict__ Wv,
                            const float* __restrict__ ln_g, const float* __restrict__ ln_b,
                            const float* __restrict__ sg) {
    int n = threadIdx.x;  // 128 threads
    if (n < DS) {
        g_wvec[n]  = expf(td[n]);
        g_efvec[n] = expf(tf[n]);
    }
    for (int i = n; i < Dq; i += 128)
        g_gate[i] = 1.f / (1.f + expf(-sg[i]));

    int j = n >> 1, isv = n & 1;
    float cs = 0.f, bs = 0.f;
    for (int k = 0; k < Dq; k++) {
        float wv = isv ? Wv[k * DS + j] : Wk[k * DS + j];
        float gk = ln_g[k];
        float w2 = gk * wv;
        __nv_bfloat16 h = __float2bfloat16(w2);
        g_W2h[k * 128 + n] = h;
        g_W2l[k * 128 + n] = __float2bfloat16(w2 - __bfloat162float(h));
        cs += w2;
        bs += ln_b[k] * wv;
    }
    g_csum[n] = cs;
    g_bsum[n] = bs;
}

// ---------------------------------------------------------------------------
__global__ void coef_kernel(const float* __restrict__ td) {
    int ch = blockIdx.x;
    int d  = threadIdx.x;
    __shared__ float p[CHq];
    float w = expf(td[ch]);
    p[d] = (d == 0) ? 1.f : 0.f;
    __syncthreads();
    for (int s = 1; s < CHq; s++) {
        float tmp = (d >= s) ? p[d - s] : 0.f;
        __syncthreads();
        if (d >= s) p[d] += w * tmp;
        __syncthreads();
    }
    g_c1[d * DS + ch] = p[d];

    float wc = expf(128.f * td[ch]);
    __syncthreads();
    if (d < Cq) p[d] = (d == 0) ? 1.f : 0.f;
    __syncthreads();
    for (int s = 1; s < Cq; s++) {
        float tmp = (d >= s && d < Cq) ? p[d - s] : 0.f;
        __syncthreads();
        if (d >= s && d < Cq) p[d] += wc * tmp;
        __syncthreads();
    }
    if (d < Cq) g_c2[d * DS + ch] = p[d];
}

// ---------------------------------------------------------------------------
// mma.sync machinery
// ---------------------------------------------------------------------------
__device__ __forceinline__ unsigned sptr(const void* p) {
    return (unsigned)__cvta_generic_to_shared(p);
}
__device__ __forceinline__ void ldsm4(unsigned* r, unsigned a) {
    asm volatile("ldmatrix.sync.aligned.m8n8.x4.shared.b16 {%0,%1,%2,%3},[%4];"
                 : "=r"(r[0]), "=r"(r[1]), "=r"(r[2]), "=r"(r[3]) : "r"(a));
}
__device__ __forceinline__ void ldsm4t(unsigned* r, unsigned a) {
    asm volatile("ldmatrix.sync.aligned.m8n8.x4.trans.shared.b16 {%0,%1,%2,%3},[%4];"
                 : "=r"(r[0]), "=r"(r[1]), "=r"(r[2]), "=r"(r[3]) : "r"(a));
}
__device__ __forceinline__ void mma_bf(float* c, const unsigned* a, unsigned b0, unsigned b1) {
    asm volatile("mma.sync.aligned.m16n8k16.row.col.f32.bf16.bf16.f32 "
                 "{%0,%1,%2,%3},{%4,%5,%6,%7},{%8,%9},{%0,%1,%2,%3};"
                 : "+f"(c[0]), "+f"(c[1]), "+f"(c[2]), "+f"(c[3])
                 : "r"(a[0]), "r"(a[1]), "r"(a[2]), "r"(a[3]), "r"(b0), "r"(b1));
}
__device__ __forceinline__ void cp16(unsigned s, const void* g) {
    asm volatile("cp.async.cg.shared.global [%0],[%1],16;\n" :: "r"(s), "l"(g));
}

#define AP 24    // A smem pitch (bf16), 48B rows (validated conflict-free)
#define BP 136   // B smem pitch (bf16), 272B rows (validated conflict-free)

// MODE 0: x_shift GEMM + gate-mix + LN-partials epilogue
// MODE 1: kv GEMM (LN folded) + wkv epilogue
// MODE 2: out GEMM (hs @ Wo)
template <int MODE>
__global__ __launch_bounds__(256, 2)
void gemm_tc(const float* __restrict__ x, float* __restrict__ out) {
    constexpr int KTOT = (MODE == 2) ? 64 : 1024;
    constexpr int NCH = KTOT / 16;

    __shared__ __nv_bfloat16 As[2][2][128 * AP];   // [stage][hi/lo]
    __shared__ __nv_bfloat16 Bs[2][2][16 * BP];

    const int t = threadIdx.x;
    const int lane = t & 31;
    const int wid = t >> 5;
    const int wm = (wid >> 2) * 64;
    const int wn = (wid & 3) * 32;
    const int bm = (MODE == 1 ? blockIdx.x : blockIdx.y) * 128;
    const int bn = (MODE == 1 ? 0 : blockIdx.x * 128);

    // ---- load geometry (R5-validated) ----
    const __nv_bfloat16 *pAh, *pAl, *pBh, *pBl;
    size_t bpitch;
    {
        int r = bm + (t >> 1);
        if (MODE == 0) {
            int s = ((r >> 13) << 13) | (((r & (Tq - 1)) + Tq / 2) & (Tq - 1));
            pAh = g_xh + (size_t)s * Dq;
            pAl = g_xl + (size_t)s * Dq;
        } else if (MODE == 1) {
            pAh = g_xsh + (size_t)r * Dq;
            pAl = g_xsl + (size_t)r * Dq;
        } else {
            pAh = g_hsh + (size_t)r * DS;
            pAl = g_hsl + (size_t)r * DS;
        }
        pAh += (t & 1) * 8;
        pAl += (t & 1) * 8;
    }
    if (MODE == 0)      { pBh = g_wshh; pBl = g_wshl; bpitch = Dq;  }
    else if (MODE == 1) { pBh = g_W2h;  pBl = g_W2l;  bpitch = 128; }
    else                { pBh = g_woh;  pBl = g_wol;  bpitch = Dq;  }
    pBh += (size_t)(t >> 4) * bpitch + bn + (t & 15) * 8;
    pBl += (size_t)(t >> 4) * bpitch + bn + (t & 15) * 8;

    const unsigned aST = (unsigned)(((t >> 1) * AP + (t & 1) * 8) * 2);
    const unsigned bST = (unsigned)(((t >> 4) * BP + (t & 15) * 8) * 2);
    const unsigned aoff = (unsigned)(((lane & 15) * AP + ((lane >> 4) << 3)) * 2);
    const unsigned boff = (unsigned)(((lane & 15) * BP + wn + ((lane >> 4) << 3)) * 2);

    float acc[4][4][4];
#pragma unroll
    for (int i = 0; i < 4; i++)
#pragma unroll
        for (int j = 0; j < 4; j++)
#pragma unroll
            for (int e = 0; e < 4; e++) acc[i][j][e] = 0.f;

    auto LOAD = [&](int kc) {
        const int s = kc & 1;
        cp16(sptr(&As[s][0][0]) + aST, pAh + (size_t)kc * 16);
        cp16(sptr(&As[s][1][0]) + aST, pAl + (size_t)kc * 16);
        cp16(sptr(&Bs[s][0][0]) + bST, pBh + (size_t)kc * 16 * bpitch);
        cp16(sptr(&Bs[s][1][0]) + bST, pBl + (size_t)kc * 16 * bpitch);
        asm volatile("cp.async.commit_group;" ::: "memory");
    };

    // ---- R5-validated loop: 2 stages, single barrier, LOAD after barrier ----
    LOAD(0);
    for (int kc = 0; kc < NCH; kc++) {
        asm volatile("cp.async.wait_group 0;" ::: "memory");
        __syncthreads();
        if (kc + 1 < NCH) LOAD(kc + 1);   // overlaps with compute below

        const int s = kc & 1;
        const unsigned aHi = sptr(&As[s][0][0]);
        const unsigned aLo = sptr(&As[s][1][0]);
        const unsigned bHi = sptr(&Bs[s][0][0]);
        const unsigned bLo = sptr(&Bs[s][1][0]);

        unsigned ah[4][4], al[4][4], bh[2][4], bl[2][4];
#pragma unroll
        for (int mt = 0; mt < 4; mt++) {
            unsigned off = (unsigned)((wm + mt * 16) * AP * 2) + aoff;
            ldsm4(ah[mt], aHi + off);
            ldsm4(al[mt], aLo + off);
        }
#pragma unroll
        for (int ng = 0; ng < 2; ng++) {
            unsigned off = boff + ng * 32;
            ldsm4t(bh[ng], bHi + off);
            ldsm4t(bl[ng], bLo + off);
        }
#pragma unroll
        for (int mt = 0; mt < 4; mt++)
#pragma unroll
            for (int nt = 0; nt < 4; nt++) {
                const int ng = nt >> 1, p = (nt & 1) * 2;
                mma_bf(acc[mt][nt], ah[mt], bh[ng][p], bh[ng][p + 1]);
                mma_bf(acc[mt][nt], ah[mt], bl[ng][p], bl[ng][p + 1]);
                mma_bf(acc[mt][nt], al[mt], bh[ng][p], bh[ng][p + 1]);
            }
    }

    // ---------------- epilogue ----------------
#pragma unroll
    for (int mt = 0; mt < 4; mt++) {
        const int r0 = bm + wm + mt * 16 + (lane >> 2);
        if (MODE == 0) {
            float s0 = 0.f, s20 = 0.f, s1 = 0.f, s21 = 0.f;
#pragma unroll
            for (int nt = 0; nt < 4; nt++) {
                const int col = bn + wn + nt * 8 + (lane & 3) * 2;
                float2 g2 = *(const float2*)&g_gate[col];
                float2 xv = *(const float2*)&x[(size_t)r0 * Dq + col];
                float ox = fmaf(acc[mt][nt][0] - xv.x, g2.x, xv.x);
                float oy = fmaf(acc[mt][nt][1] - xv.y, g2.y, xv.y);
                s0 += ox + oy;
                s20 += ox * ox + oy * oy;
                __nv_bfloat162 h, l;
                split2(ox, oy, h, l);
                *(__nv_bfloat162*)&g_xsh[(size_t)r0 * Dq + col] = h;
                *(__nv_bfloat162*)&g_xsl[(size_t)r0 * Dq + col] = l;
                float2 xw = *(const float2*)&x[(size_t)(r0 + 8) * Dq + col];
                ox = fmaf(acc[mt][nt][2] - xw.x, g2.x, xw.x);
                oy = fmaf(acc[mt][nt][3] - xw.y, g2.y, xw.y);
                s1 += ox + oy;
                s21 += ox * ox + oy * oy;
                split2(ox, oy, h, l);
                *(__nv_bfloat162*)&g_xsh[(size_t)(r0 + 8) * Dq + col] = h;
                *(__nv_bfloat162*)&g_xsl[(size_t)(r0 + 8) * Dq + col] = l;
            }
#pragma unroll
            for (int o = 1; o <= 2; o <<= 1) {
                s0  += __shfl_xor_sync(0xffffffffu, s0, o);
                s20 += __shfl_xor_sync(0xffffffffu, s20, o);
                s1  += __shfl_xor_sync(0xffffffffu, s1, o);
                s21 += __shfl_xor_sync(0xffffffffu, s21, o);
            }
            if ((lane & 3) == 0) {
                const int slice = blockIdx.x * 4 + (wid & 3);
                g_ps[(size_t)slice * ROWS + r0]      = s0;
                g_ps2[(size_t)slice * ROWS + r0]     = s20;
                g_ps[(size_t)slice * ROWS + r0 + 8]  = s1;
                g_ps2[(size_t)slice * ROWS + r0 + 8] = s21;
            }
        } else if (MODE == 1) {
            const float mu0 = g_mu[r0], rs0 = g_rstd[r0];
            const float mu1 = g_mu[r0 + 8], rs1 = g_rstd[r0 + 8];
#pragma unroll
            for (int nt = 0; nt < 4; nt++) {
                const int col = wn + nt * 8 + (lane & 3) * 2;
                const int ch = col >> 1;
                const float cs0 = g_csum[col], cs1 = g_csum[col + 1];
                const float bs0 = g_bsum[col], bs1 = g_bsum[col + 1];
                const float ef = g_efvec[ch];
                {
                    float kk = rs0 * (acc[mt][nt][0] - mu0 * cs0) + bs0;
                    float vv = rs0 * (acc[mt][nt][1] - mu0 * cs1) + bs1;
                    float sig = 1.f / (1.f + expf(-kk));
                    g_wkv[(size_t)r0 * DS + ch] = expf(-ef * sig) * vv;
                }
                {
                    float kk = rs1 * (acc[mt][nt][2] - mu1 * cs0) + bs0;
                    float vv = rs1 * (acc[mt][nt][3] - mu1 * cs1) + bs1;
                    float sig = 1.f / (1.f + expf(-kk));
                    g_wkv[(size_t)(r0 + 8) * DS + ch] = expf(-ef * sig) * vv;
                }
            }
        } else {
#pragma unroll
            for (int nt = 0; nt < 4; nt++) {
                const int col = bn + wn + nt * 8 + (lane & 3) * 2;
                float2 o0 = {acc[mt][nt][0], acc[mt][nt][1]};
                float2 o1 = {acc[mt][nt][2], acc[mt][nt][3]};
                *(float2*)&out[(size_t)r0 * Dq + col] = o0;
                *(float2*)&out[(size_t)(r0 + 8) * Dq + col] = o1;
            }
        }
    }
}

// ---------------------------------------------------------------------------
__global__ void finalize_stats() {
    int row = blockIdx.x * 256 + threadIdx.x;
    float s = 0.f, s2 = 0.f;
#pragma unroll
    for (int sl = 0; sl < 32; sl++) {
        s  += g_ps[(size_t)sl * ROWS + row];
        s2 += g_ps2[(size_t)sl * ROWS + row];
    }
    float mu  = s * (1.f / 1024.f);
    float var = s2 * (1.f / 1024.f) - mu * mu;
    g_mu[row]   = mu;
    g_rstd[row] = rsqrtf(var + 1e-5f);
}

// ---------------------------------------------------------------------------
__global__ void scan_kernel() {
    int bc = blockIdx.x;
    int ch = threadIdx.x;
    float w = g_wvec[ch];
    size_t base = (size_t)bc * CHq * DS + ch;
    float h = 0.f;
    for (int i = 0; i < CHq; i++) {
        h = fmaf(h, w, g_wkv[base + (size_t)i * DS]);
        __nv_bfloat16 hh = __float2bfloat16(h);
        g_hsh[base + (size_t)i * DS] = hh;
        g_hsl[base + (size_t)i * DS] = __float2bfloat16(h - __bfloat162float(hh));
    }
}

// ---------------------------------------------------------------------------
__global__ void cstate_kernel() {
    int bc = blockIdx.x;
    int ch = threadIdx.x;
    const float* base = g_wkv + (size_t)bc * CHq * DS + ch;
    float s = 0.f;
    for (int d = 0; d < CHq; d++)
        s = fmaf(g_c1[d * DS + ch], base[(size_t)(CHq - 1 - d) * DS], s);
    g_cs[bc * DS + ch] = s;
}

__global__ void lstate_kernel(float* __restrict__ outls) {
    int b = blockIdx.x;
    int ch = threadIdx.x;
    float s = 0.f;
    for (int e = 0; e < Cq; e++)
        s = fmaf(g_c2[e * DS + ch], g_cs[((size_t)b * Cq + (Cq - 1 - e)) * DS + ch], s);
    outls[b * DS + ch] = s;
}

// ---------------------------------------------------------------------------
extern "C" void kernel_launch(void* const* d_in, const int* in_sizes, int n_in,
                              void* d_out, int out_size) {
    const float* x   = (const float*)d_in[0];
    const float* td  = (const float*)d_in[1];
    const float* tf  = (const float*)d_in[2];
    const float* Wk  = (const float*)d_in[3];
    const float* Wv  = (const float*)d_in[4];
    const float* Wo  = (const float*)d_in[5];
    const float* Wsh = (const float*)d_in[6];
    const float* sg  = (const float*)d_in[7];
    const float* lng = (const float*)d_in[8];
    const float* lnb = (const float*)d_in[9];
    float* out = (float*)d_out;

    __nv_bfloat16 *xh, *xl, *wshh, *wshl, *woh, *wol;
    cudaGetSymbolAddress((void**)&xh,   g_xh);
    cudaGetSymbolAddress((void**)&xl,   g_xl);
    cudaGetSymbolAddress((void**)&wshh, g_wshh);
    cudaGetSymbolAddress((void**)&wshl, g_wshl);
    cudaGetSymbolAddress((void**)&woh,  g_woh);
    cudaGetSymbolAddress((void**)&wol,  g_wol);

    // launch order chosen so gemm_tc<0> is the 4th launch (ncu samples #4)
    conv_split<<<(ROWS * Dq / 4) / 256, 256>>>(x, xh, xl);               // 1
    conv_split<<<(Dq * Dq / 4) / 256, 256>>>(Wsh, wshh, wshl);           // 2
    prep_kernel<<<1, 128>>>(td, tf, Wk, Wv, lng, lnb, sg);               // 3
    gemm_tc<0><<<dim3(Dq / 128, ROWS / 128), 256>>>(x, out);             // 4 <- profiled
    finalize_stats<<<ROWS / 256, 256>>>();                               // 5
    coef_kernel<<<64, 128>>>(td);                                        // 6
    conv_split<<<(DS * Dq / 4) / 256, 256>>>(Wo, woh, wol);              // 7
    gemm_tc<1><<<ROWS / 128, 256>>>(x, out);                             // 8
    scan_kernel<<<Bq * Cq, DS>>>();                                      // 9
    gemm_tc<2><<<dim3(Dq / 128, ROWS / 128), 256>>>(x, out);             // 10
    cstate_kernel<<<Bq * Cq, DS>>>();                                    // 11
    if ((size_t)out_size >= OUT_ELEMS + (size_t)Bq * DS) {
        lstate_kernel<<<Bq, DS>>>(out + OUT_ELEMS);                      // 12
    }
}